// round 1
// baseline (speedup 1.0000x reference)
#include <cuda_runtime.h>

// VectorQuantizer: B=8,S=64,N=128,D=128, K=1024
// T = 65536 tokens. Outputs: x_q [T*128] f32 then loss [512] f32.

#define TT 65536
#define DD 128
#define KK 1024
#define GROUPS 512      // B*S
#define XS_STRIDE 132   // 128 + 4 pad (keeps 16B alignment, spreads banks)

__device__ int   g_idx[TT];
__device__ float g_cbnorm[KK];
__device__ float g_loss_dummy[GROUPS];

// ---------------------------------------------------------------------------
// Kernel 1: ||e_k||^2 for each codebook row. One warp per code.
// ---------------------------------------------------------------------------
__global__ void k_cbnorm(const float* __restrict__ cb) {
    int warp = threadIdx.x >> 5, lane = threadIdx.x & 31;
    int k = (blockIdx.x << 3) + warp;
    float4 v = reinterpret_cast<const float4*>(cb)[k * 32 + lane];
    float s = v.x * v.x + v.y * v.y + v.z * v.z + v.w * v.w;
#pragma unroll
    for (int o = 16; o; o >>= 1) s += __shfl_xor_sync(0xffffffffu, s, o);
    if (lane == 0) g_cbnorm[k] = s;
}

// ---------------------------------------------------------------------------
// Kernel 2: distance GEMM + fused argmin.
// CTA tile: 128 tokens x 128 codes/chunk, 8 chunks over K=1024.
// 256 threads, 8x8 register microtile (split 4+4 for conflict-free LDS.128).
// dist = ||e||^2 - 2 x.e   (||x||^2 constant per token -> irrelevant to argmin)
// ---------------------------------------------------------------------------
__global__ __launch_bounds__(256, 1)
void k_dist_argmin(const float* __restrict__ x, const float* __restrict__ cb) {
    extern __shared__ float sm[];
    float* xs  = sm;                       // [128 d][132] token-contiguous
    float* es  = sm + DD * XS_STRIDE;      // [128 d][132] code-contiguous
    float* cbn = es + DD * XS_STRIDE;      // [128]

    const int tid = threadIdx.x;
    const int tx = tid & 15;               // code dim (16 threads)
    const int ty = tid >> 4;               // token dim (16 threads)
    const int tok0 = blockIdx.x << 7;

    // Load x tile transposed into smem: warp reads one token row (coalesced),
    // scatters 4 scalars per float4 into d-major layout.
    {
        const float4* xp = reinterpret_cast<const float4*>(x) + (size_t)tok0 * 32;
        for (int v = tid; v < 4096; v += 256) {
            int t = v >> 5, dv = v & 31;
            float4 val = xp[t * 32 + dv];
            int base = (dv << 2) * XS_STRIDE + t;
            xs[base                ] = val.x;
            xs[base +     XS_STRIDE] = val.y;
            xs[base + 2 * XS_STRIDE] = val.z;
            xs[base + 3 * XS_STRIDE] = val.w;
        }
    }

    float bestv[8];
    int   besti[8];
#pragma unroll
    for (int i = 0; i < 8; i++) { bestv[i] = __int_as_float(0x7f800000); besti[i] = 0; }

    for (int ch = 0; ch < 8; ch++) {
        const int cb0 = ch << 7;
        __syncthreads();
        {
            const float4* ep = reinterpret_cast<const float4*>(cb) + (size_t)cb0 * 32;
            for (int v = tid; v < 4096; v += 256) {
                int c = v >> 5, dv = v & 31;
                float4 val = ep[c * 32 + dv];
                int base = (dv << 2) * XS_STRIDE + c;
                es[base                ] = val.x;
                es[base +     XS_STRIDE] = val.y;
                es[base + 2 * XS_STRIDE] = val.z;
                es[base + 3 * XS_STRIDE] = val.w;
            }
            if (tid < 128) cbn[tid] = g_cbnorm[cb0 + tid];
        }
        __syncthreads();

        float acc[8][8];
#pragma unroll
        for (int i = 0; i < 8; i++)
#pragma unroll
            for (int j = 0; j < 8; j++) acc[i][j] = 0.0f;

#pragma unroll 4
        for (int d = 0; d < DD; d++) {
            const float* xr = xs + d * XS_STRIDE;
            const float* er = es + d * XS_STRIDE;
            float4 xa = *reinterpret_cast<const float4*>(xr + (ty << 2));
            float4 xb = *reinterpret_cast<const float4*>(xr + (ty << 2) + 64);
            float4 ea = *reinterpret_cast<const float4*>(er + (tx << 2));
            float4 eb = *reinterpret_cast<const float4*>(er + (tx << 2) + 64);
            float xv[8] = {xa.x, xa.y, xa.z, xa.w, xb.x, xb.y, xb.z, xb.w};
            float ev[8] = {ea.x, ea.y, ea.z, ea.w, eb.x, eb.y, eb.z, eb.w};
#pragma unroll
            for (int i = 0; i < 8; i++)
#pragma unroll
                for (int j = 0; j < 8; j++)
                    acc[i][j] = fmaf(xv[i], ev[j], acc[i][j]);
        }

        // Fused argmin epilogue: per-thread min over 8 codes (ascending index,
        // strict < keeps lowest index), butterfly across the 16 code-lanes,
        // then merge into the running min (strict < keeps earlier chunk).
#pragma unroll
        for (int i = 0; i < 8; i++) {
            float bv = __int_as_float(0x7f800000);
            int bi = 0x7fffffff;
#pragma unroll
            for (int j = 0; j < 8; j++) {
                int cl = (j < 4) ? ((tx << 2) + j) : (64 + (tx << 2) + (j - 4));
                float dist = cbn[cl] - 2.0f * acc[i][j];
                if (dist < bv) { bv = dist; bi = cb0 + cl; }
            }
#pragma unroll
            for (int o = 1; o < 16; o <<= 1) {
                float ov = __shfl_xor_sync(0xffffffffu, bv, o);
                int   oi = __shfl_xor_sync(0xffffffffu, bi, o);
                if (ov < bv || (ov == bv && oi < bi)) { bv = ov; bi = oi; }
            }
            if (bv < bestv[i] || (bv == bestv[i] && bi < besti[i])) {
                bestv[i] = bv; besti[i] = bi;
            }
        }
    }

    if (tx == 0) {
#pragma unroll
        for (int i = 0; i < 8; i++) {
            int tl = (i < 4) ? ((ty << 2) + i) : (64 + (ty << 2) + (i - 4));
            g_idx[tok0 + tl] = besti[i];
        }
    }
}

// ---------------------------------------------------------------------------
// Kernel 3: gather x_q = x + (c - x)  (mirrors straight-through arithmetic)
// and loss[b,s] = 1.25 * mean_{n,d} (x_q - x)^2. Deterministic block reduce.
// One block per (b,s) group of 128 tokens; one warp handles 16 tokens.
// ---------------------------------------------------------------------------
__global__ __launch_bounds__(256)
void k_gather_loss(const float* __restrict__ x, const float* __restrict__ cb,
                   float* __restrict__ xq, float* __restrict__ loss) {
    int g = blockIdx.x;
    int warp = threadIdx.x >> 5, lane = threadIdx.x & 31;
    int tok0 = g << 7;
    float acc = 0.0f;
    const float4* xp = reinterpret_cast<const float4*>(x);
    const float4* cp = reinterpret_cast<const float4*>(cb);
    float4* qp = reinterpret_cast<float4*>(xq);

#pragma unroll 4
    for (int it = 0; it < 16; it++) {
        int t = tok0 + (warp << 4) + it;
        int idx = g_idx[t];
        float4 c4 = cp[(size_t)idx * 32 + lane];
        float4 x4 = xp[(size_t)t * 32 + lane];
        float4 q4;
        q4.x = x4.x + (c4.x - x4.x);
        q4.y = x4.y + (c4.y - x4.y);
        q4.z = x4.z + (c4.z - x4.z);
        q4.w = x4.w + (c4.w - x4.w);
        float d0 = q4.x - x4.x;
        float d1 = q4.y - x4.y;
        float d2 = q4.z - x4.z;
        float d3 = q4.w - x4.w;
        acc += d0 * d0 + d1 * d1 + d2 * d2 + d3 * d3;
        qp[(size_t)t * 32 + lane] = q4;
    }
#pragma unroll
    for (int o = 16; o; o >>= 1) acc += __shfl_xor_sync(0xffffffffu, acc, o);

    __shared__ float ws[8];
    if (lane == 0) ws[warp] = acc;
    __syncthreads();
    if (threadIdx.x == 0) {
        float s = 0.0f;
#pragma unroll
        for (int w = 0; w < 8; w++) s += ws[w];
        loss[g] = s * (1.25f / 16384.0f);
    }
}

// ---------------------------------------------------------------------------
extern "C" void kernel_launch(void* const* d_in, const int* in_sizes, int n_in,
                              void* d_out, int out_size) {
    const float* x  = (const float*)d_in[0];   // [T, 128]
    const float* cb = (const float*)d_in[1];   // [1024, 128]
    float* xq = (float*)d_out;

    // loss lives right after x_q if the output buffer includes it
    float* loss;
    if (out_size >= TT * DD + GROUPS) {
        loss = xq + (size_t)TT * DD;
    } else {
        void* p = nullptr;
        cudaGetSymbolAddress(&p, g_loss_dummy);
        loss = (float*)p;
    }

    const int smem_bytes = (2 * DD * XS_STRIDE + 128) * (int)sizeof(float); // 135680
    cudaFuncSetAttribute(k_dist_argmin,
                         cudaFuncAttributeMaxDynamicSharedMemorySize, smem_bytes);

    k_cbnorm<<<KK / 8, 256>>>(cb);
    k_dist_argmin<<<TT / 128, 256, smem_bytes>>>(x, cb);
    k_gather_loss<<<GROUPS, 256>>>(x, cb, xq, loss);
}

// round 2
// speedup vs baseline: 1.0025x; 1.0025x over previous
#include <cuda_runtime.h>

// VectorQuantizer: B=8,S=64,N=128,D=128, K=1024
// T = 65536 tokens. Outputs: x_q [T*128] f32 then loss [512] f32.

#define TT 65536
#define DD 128
#define KK 1024
#define GROUPS 512      // B*S
#define XS_STRIDE 132   // 128 + 4 pad (keeps 16B alignment, spreads banks)

__device__ int   g_idx[TT];
__device__ float g_cbnorm[KK];
__device__ float g_loss_dummy[GROUPS];

// ---------------------------------------------------------------------------
// Kernel 1: ||e_k||^2 for each codebook row. One warp per code.
// ---------------------------------------------------------------------------
__global__ void k_cbnorm(const float* __restrict__ cb) {
    int warp = threadIdx.x >> 5, lane = threadIdx.x & 31;
    int k = (blockIdx.x << 3) + warp;
    float4 v = reinterpret_cast<const float4*>(cb)[k * 32 + lane];
    float s = v.x * v.x + v.y * v.y + v.z * v.z + v.w * v.w;
#pragma unroll
    for (int o = 16; o; o >>= 1) s += __shfl_xor_sync(0xffffffffu, s, o);
    if (lane == 0) g_cbnorm[k] = s;
}

// ---------------------------------------------------------------------------
// Kernel 2: distance GEMM + fused argmin.
// CTA tile: 128 tokens x 128 codes/chunk, 8 chunks over K=1024.
// 256 threads, 8x8 register microtile (split 4+4 for conflict-free LDS.128).
// dist = ||e||^2 - 2 x.e   (||x||^2 constant per token -> irrelevant to argmin)
// ---------------------------------------------------------------------------
__global__ __launch_bounds__(256, 1)
void k_dist_argmin(const float* __restrict__ x, const float* __restrict__ cb) {
    extern __shared__ float sm[];
    float* xs  = sm;                       // [128 d][132] token-contiguous
    float* es  = sm + DD * XS_STRIDE;      // [128 d][132] code-contiguous
    float* cbn = es + DD * XS_STRIDE;      // [128]

    const int tid = threadIdx.x;
    const int tx = tid & 15;               // code dim (16 threads)
    const int ty = tid >> 4;               // token dim (16 threads)
    const int tok0 = blockIdx.x << 7;

    // Load x tile transposed into smem: warp reads one token row (coalesced),
    // scatters 4 scalars per float4 into d-major layout.
    {
        const float4* xp = reinterpret_cast<const float4*>(x) + (size_t)tok0 * 32;
        for (int v = tid; v < 4096; v += 256) {
            int t = v >> 5, dv = v & 31;
            float4 val = xp[t * 32 + dv];
            int base = (dv << 2) * XS_STRIDE + t;
            xs[base                ] = val.x;
            xs[base +     XS_STRIDE] = val.y;
            xs[base + 2 * XS_STRIDE] = val.z;
            xs[base + 3 * XS_STRIDE] = val.w;
        }
    }

    float bestv[8];
    int   besti[8];
#pragma unroll
    for (int i = 0; i < 8; i++) { bestv[i] = __int_as_float(0x7f800000); besti[i] = 0; }

    for (int ch = 0; ch < 8; ch++) {
        const int cb0 = ch << 7;
        __syncthreads();
        {
            const float4* ep = reinterpret_cast<const float4*>(cb) + (size_t)cb0 * 32;
            for (int v = tid; v < 4096; v += 256) {
                int c = v >> 5, dv = v & 31;
                float4 val = ep[c * 32 + dv];
                int base = (dv << 2) * XS_STRIDE + c;
                es[base                ] = val.x;
                es[base +     XS_STRIDE] = val.y;
                es[base + 2 * XS_STRIDE] = val.z;
                es[base + 3 * XS_STRIDE] = val.w;
            }
            if (tid < 128) cbn[tid] = g_cbnorm[cb0 + tid];
        }
        __syncthreads();

        float acc[8][8];
#pragma unroll
        for (int i = 0; i < 8; i++)
#pragma unroll
            for (int j = 0; j < 8; j++) acc[i][j] = 0.0f;

#pragma unroll 4
        for (int d = 0; d < DD; d++) {
            const float* xr = xs + d * XS_STRIDE;
            const float* er = es + d * XS_STRIDE;
            float4 xa = *reinterpret_cast<const float4*>(xr + (ty << 2));
            float4 xb = *reinterpret_cast<const float4*>(xr + (ty << 2) + 64);
            float4 ea = *reinterpret_cast<const float4*>(er + (tx << 2));
            float4 eb = *reinterpret_cast<const float4*>(er + (tx << 2) + 64);
            float xv[8] = {xa.x, xa.y, xa.z, xa.w, xb.x, xb.y, xb.z, xb.w};
            float ev[8] = {ea.x, ea.y, ea.z, ea.w, eb.x, eb.y, eb.z, eb.w};
#pragma unroll
            for (int i = 0; i < 8; i++)
#pragma unroll
                for (int j = 0; j < 8; j++)
                    acc[i][j] = fmaf(xv[i], ev[j], acc[i][j]);
        }

        // Fused argmin epilogue: per-thread min over 8 codes (ascending index,
        // strict < keeps lowest index), butterfly across the 16 code-lanes,
        // then merge into the running min (strict < keeps earlier chunk).
#pragma unroll
        for (int i = 0; i < 8; i++) {
            float bv = __int_as_float(0x7f800000);
            int bi = 0x7fffffff;
#pragma unroll
            for (int j = 0; j < 8; j++) {
                int cl = (j < 4) ? ((tx << 2) + j) : (64 + (tx << 2) + (j - 4));
                float dist = cbn[cl] - 2.0f * acc[i][j];
                if (dist < bv) { bv = dist; bi = cb0 + cl; }
            }
#pragma unroll
            for (int o = 1; o < 16; o <<= 1) {
                float ov = __shfl_xor_sync(0xffffffffu, bv, o);
                int   oi = __shfl_xor_sync(0xffffffffu, bi, o);
                if (ov < bv || (ov == bv && oi < bi)) { bv = ov; bi = oi; }
            }
            if (bv < bestv[i] || (bv == bestv[i] && bi < besti[i])) {
                bestv[i] = bv; besti[i] = bi;
            }
        }
    }

    if (tx == 0) {
#pragma unroll
        for (int i = 0; i < 8; i++) {
            int tl = (i < 4) ? ((ty << 2) + i) : (64 + (ty << 2) + (i - 4));
            g_idx[tok0 + tl] = besti[i];
        }
    }
}

// ---------------------------------------------------------------------------
// Kernel 3: gather x_q = x + (c - x)  (mirrors straight-through arithmetic)
// and loss[b,s] = 1.25 * mean_{n,d} (x_q - x)^2. Deterministic block reduce.
// One block per (b,s) group of 128 tokens; one warp handles 16 tokens.
// ---------------------------------------------------------------------------
__global__ __launch_bounds__(256)
void k_gather_loss(const float* __restrict__ x, const float* __restrict__ cb,
                   float* __restrict__ xq, float* __restrict__ loss) {
    int g = blockIdx.x;
    int warp = threadIdx.x >> 5, lane = threadIdx.x & 31;
    int tok0 = g << 7;
    float acc = 0.0f;
    const float4* xp = reinterpret_cast<const float4*>(x);
    const float4* cp = reinterpret_cast<const float4*>(cb);
    float4* qp = reinterpret_cast<float4*>(xq);

#pragma unroll 4
    for (int it = 0; it < 16; it++) {
        int t = tok0 + (warp << 4) + it;
        int idx = g_idx[t];
        float4 c4 = cp[(size_t)idx * 32 + lane];
        float4 x4 = xp[(size_t)t * 32 + lane];
        float4 q4;
        q4.x = x4.x + (c4.x - x4.x);
        q4.y = x4.y + (c4.y - x4.y);
        q4.z = x4.z + (c4.z - x4.z);
        q4.w = x4.w + (c4.w - x4.w);
        float d0 = q4.x - x4.x;
        float d1 = q4.y - x4.y;
        float d2 = q4.z - x4.z;
        float d3 = q4.w - x4.w;
        acc += d0 * d0 + d1 * d1 + d2 * d2 + d3 * d3;
        qp[(size_t)t * 32 + lane] = q4;
    }
#pragma unroll
    for (int o = 16; o; o >>= 1) acc += __shfl_xor_sync(0xffffffffu, acc, o);

    __shared__ float ws[8];
    if (lane == 0) ws[warp] = acc;
    __syncthreads();
    if (threadIdx.x == 0) {
        float s = 0.0f;
#pragma unroll
        for (int w = 0; w < 8; w++) s += ws[w];
        loss[g] = s * (1.25f / 16384.0f);
    }
}

// ---------------------------------------------------------------------------
extern "C" void kernel_launch(void* const* d_in, const int* in_sizes, int n_in,
                              void* d_out, int out_size) {
    const float* x  = (const float*)d_in[0];   // [T, 128]
    const float* cb = (const float*)d_in[1];   // [1024, 128]
    float* xq = (float*)d_out;

    // loss lives right after x_q if the output buffer includes it
    float* loss;
    if (out_size >= TT * DD + GROUPS) {
        loss = xq + (size_t)TT * DD;
    } else {
        void* p = nullptr;
        cudaGetSymbolAddress(&p, g_loss_dummy);
        loss = (float*)p;
    }

    const int smem_bytes = (2 * DD * XS_STRIDE + 128) * (int)sizeof(float); // 135680
    cudaFuncSetAttribute(k_dist_argmin,
                         cudaFuncAttributeMaxDynamicSharedMemorySize, smem_bytes);

    k_cbnorm<<<KK / 8, 256>>>(cb);
    k_dist_argmin<<<TT / 128, 256, smem_bytes>>>(x, cb);
    k_gather_loss<<<GROUPS, 256>>>(x, cb, xq, loss);
}

// round 6
// speedup vs baseline: 2.9133x; 2.9060x over previous
#include <cuda_runtime.h>
#include <cuda_bf16.h>
#include <stdint.h>

#define TT 65536
#define DD 128
#define KK 1024
#define GROUPS 512

// baked codebook: 1024 rows x 144 bf16 (cols 0..127 = e, 128/129 = -||e||^2/2 split, rest 0)
__device__ uint4  Eb[KK * 18];          // 288 B per row
__device__ float  g_cbnorm[KK];
__device__ uint2  g_cand[TT * 24];      // per token: 8 subsets x top-3 (v_bits, idx)
__device__ float  g_tokloss[TT];
__device__ float  g_loss_dummy[GROUPS];

__device__ __forceinline__ uint32_t smem_u32(const void* p) {
    uint32_t a;
    asm("{ .reg .u64 t; cvta.to.shared.u64 t, %1; cvt.u32.u64 %0, t; }" : "=r"(a) : "l"(p));
    return a;
}
__device__ __forceinline__ uint32_t bf2u(float a, float b) {
    __nv_bfloat162 t = __floats2bfloat162_rn(a, b);
    return *reinterpret_cast<uint32_t*>(&t);
}
#define CP_ASYNC16(s, g) asm volatile("cp.async.cg.shared.global [%0], [%1], 16;" :: "r"(s), "l"(g) : "memory")
#define CP_COMMIT()      asm volatile("cp.async.commit_group;" ::: "memory")
#define CP_WAIT(n)       asm volatile("cp.async.wait_group %0;" :: "n"(n) : "memory")

#define LDSM4(r0, r1, r2, r3, a) \
    asm volatile("ldmatrix.sync.aligned.m8n8.x4.shared.b16 {%0,%1,%2,%3}, [%4];" \
        : "=r"(r0), "=r"(r1), "=r"(r2), "=r"(r3) : "r"(a))

#define MMA16816(d, a, b) \
    asm volatile("mma.sync.aligned.m16n8k16.row.col.f32.bf16.bf16.f32 " \
        "{%0,%1,%2,%3}, {%4,%5,%6,%7}, {%8,%9}, {%0,%1,%2,%3};" \
        : "+f"((d)[0]), "+f"((d)[1]), "+f"((d)[2]), "+f"((d)[3]) \
        : "r"((a)[0]), "r"((a)[1]), "r"((a)[2]), "r"((a)[3]), "r"((b)[0]), "r"((b)[1]))

// SMEM: A 128x152 bf16 (304B stride) | B0 128x152 | B1 128x152
#define A_BYTES   38912
#define SMEM_SZ   (3 * A_BYTES)

// ---------------------------------------------------------------------------
// Prep: codebook -> bf16 rows + norm terms. One warp per code.
// ---------------------------------------------------------------------------
__global__ void k_prep(const float* __restrict__ cb) {
    int warp = threadIdx.x >> 5, lane = threadIdx.x & 31;
    int k = (blockIdx.x << 3) + warp;
    float4 v = reinterpret_cast<const float4*>(cb)[k * 32 + lane];
    float n = v.x * v.x + v.y * v.y + v.z * v.z + v.w * v.w;
#pragma unroll
    for (int o = 16; o; o >>= 1) n += __shfl_xor_sync(0xffffffffu, n, o);
    uint2* row = reinterpret_cast<uint2*>(Eb) + (size_t)k * 36;
    uint2 w;
    w.x = bf2u(v.x, v.y); w.y = bf2u(v.z, v.w);
    row[lane] = w;
    if (lane == 0) {
        g_cbnorm[k] = n;
        float m = -0.5f * n;
        __nv_bfloat16 h = __float2bfloat16_rn(m);
        float lo = m - __bfloat162float(h);
        uint2 z; z.x = bf2u(m, lo); z.y = 0u;
        row[32] = z;
        uint2 zz; zz.x = 0u; zz.y = 0u;
        row[33] = zz;
    }
    if (lane == 1) {
        uint2 zz; zz.x = 0u; zz.y = 0u;
        row[34] = zz; row[35] = zz;
    }
}

// ---------------------------------------------------------------------------
// GEMM: s[t][k] = x_t . e_k - ||e_k||^2/2 via mma.sync bf16, per-subset top-3.
// CTA: 128 tokens x 1024 codes (8 chunks of 128). 8 warps = 4(m) x 2(n).
// ---------------------------------------------------------------------------
__global__ __launch_bounds__(256, 1)
void k_gemm(const float* __restrict__ x) {
    extern __shared__ char smc[];
    const uint32_t sb = smem_u32(smc);
    const int tid = threadIdx.x, warp = tid >> 5, lane = tid & 31;
    const int warp_m = warp >> 1, warp_n = warp & 1;
    const int tok0 = blockIdx.x << 7;

    // Build A: 128 rows x 144 cols (bf16). Thread: row tid/2, half tid&1.
    {
        int r = tid >> 1, h = tid & 1;
        const float4* xr = reinterpret_cast<const float4*>(x + (size_t)(tok0 + r) * 128 + h * 64);
        char* dst = smc + r * 304 + h * 128;
#pragma unroll
        for (int i = 0; i < 8; i++) {
            float4 a = xr[i * 2], b = xr[i * 2 + 1];
            uint4 u;
            u.x = bf2u(a.x, a.y); u.y = bf2u(a.z, a.w);
            u.z = bf2u(b.x, b.y); u.w = bf2u(b.z, b.w);
            *reinterpret_cast<uint4*>(dst + i * 16) = u;
        }
        if (h == 1) {   // cols 128..143: {1,1,0,...}
            uint4 u1; u1.x = bf2u(1.0f, 1.0f); u1.y = 0u; u1.z = 0u; u1.w = 0u;
            *reinterpret_cast<uint4*>(smc + r * 304 + 256) = u1;
            uint4 u0; u0.x = 0u; u0.y = 0u; u0.z = 0u; u0.w = 0u;
            *reinterpret_cast<uint4*>(smc + r * 304 + 272) = u0;
        }
    }

    // prefetch B chunk 0
    {
        const char* src = reinterpret_cast<const char*>(Eb);
        uint32_t bs = sb + A_BYTES;
#pragma unroll
        for (int j = 0; j < 9; j++) {
            int e = tid + j * 256;      // 2304 transfers of 16B
            int row = e / 18, c = e % 18;
            CP_ASYNC16(bs + row * 304 + c * 16, src + row * 288 + c * 16);
        }
        CP_COMMIT();
    }

    float v0[4], v1[4], v2[4];
    int   i0[4], i1[4], i2[4];
#pragma unroll
    for (int s = 0; s < 4; s++) {
        v0[s] = v1[s] = v2[s] = __int_as_float(0xff800000);
        i0[s] = i1[s] = i2[s] = 0x7fffffff;
    }

    __syncthreads();   // A + first prefetch issued

    for (int c = 0; c < 8; c++) {
        if (c + 1 < 8) {
            const char* src = reinterpret_cast<const char*>(Eb) + (size_t)(c + 1) * 36864;
            uint32_t bs = sb + A_BYTES + ((c + 1) & 1) * A_BYTES;
#pragma unroll
            for (int j = 0; j < 9; j++) {
                int e = tid + j * 256;
                int row = e / 18, cc = e % 18;
                CP_ASYNC16(bs + row * 304 + cc * 16, src + row * 288 + cc * 16);
            }
            CP_COMMIT();
            CP_WAIT(1);
        } else {
            CP_WAIT(0);
        }
        __syncthreads();   // chunk c resident in buffer c&1

        const uint32_t Bb = sb + A_BYTES + (c & 1) * A_BYTES;
        float acc[2][8][4];
#pragma unroll
        for (int mb = 0; mb < 2; mb++)
#pragma unroll
            for (int nb = 0; nb < 8; nb++)
#pragma unroll
                for (int d = 0; d < 4; d++) acc[mb][nb][d] = 0.0f;

        const uint32_t aAddr0 = sb + (warp_m * 32 + (lane & 15)) * 304 + (lane >> 4) * 16;
        const uint32_t bAddr0 = Bb + (warp_n * 64 + ((lane >> 4) << 3) + (lane & 7)) * 304;
        const uint32_t bHalf = ((lane >> 3) & 1) * 16;

#pragma unroll
        for (int k = 0; k < 9; k++) {
            uint32_t a[2][4];
#pragma unroll
            for (int mb = 0; mb < 2; mb++)
                LDSM4(a[mb][0], a[mb][1], a[mb][2], a[mb][3],
                      aAddr0 + mb * 16 * 304 + k * 32);
            uint32_t b[4][4];
#pragma unroll
            for (int np = 0; np < 4; np++)
                LDSM4(b[np][0], b[np][1], b[np][2], b[np][3],
                      bAddr0 + np * 16 * 304 + bHalf + k * 32);
#pragma unroll
            for (int mb = 0; mb < 2; mb++)
#pragma unroll
                for (int np = 0; np < 4; np++) {
                    MMA16816(acc[mb][np * 2],     a[mb], (&b[np][0]));
                    MMA16816(acc[mb][np * 2 + 1], a[mb], (&b[np][2]));
                }
        }

        // per-lane top-3 insertion (strict > keeps lowest index on ties)
        const int base = c * 128 + warp_n * 64 + ((lane & 3) << 1);
#pragma unroll
        for (int mb = 0; mb < 2; mb++)
#pragma unroll
            for (int dd = 0; dd < 2; dd++) {
                const int s = mb * 2 + dd;
#pragma unroll
                for (int nb = 0; nb < 8; nb++)
#pragma unroll
                    for (int e = 0; e < 2; e++) {
                        float vv = acc[mb][nb][dd * 2 + e];
                        if (vv > v2[s]) {
                            int idx = base + nb * 8 + e;
                            if (vv > v0[s]) {
                                v2[s] = v1[s]; i2[s] = i1[s];
                                v1[s] = v0[s]; i1[s] = i0[s];
                                v0[s] = vv;    i0[s] = idx;
                            } else if (vv > v1[s]) {
                                v2[s] = v1[s]; i2[s] = i1[s];
                                v1[s] = vv;    i1[s] = idx;
                            } else {
                                v2[s] = vv;    i2[s] = idx;
                            }
                        }
                    }
            }
        __syncthreads();   // done reading buffer c&1
    }

    // 8 disjoint subsets per token: (warp_n, lane&3). No collisions.
    const int sub = warp_n * 4 + (lane & 3);
#pragma unroll
    for (int s = 0; s < 4; s++) {
        int token = tok0 + warp_m * 32 + (s >> 1) * 16 + (lane >> 2) + (s & 1) * 8;
        uint2* dst = g_cand + (size_t)token * 24 + sub * 3;
        dst[0] = make_uint2(__float_as_uint(v0[s]), (uint32_t)i0[s]);
        dst[1] = make_uint2(__float_as_uint(v1[s]), (uint32_t)i1[s]);
        dst[2] = make_uint2(__float_as_uint(v2[s]), (uint32_t)i2[s]);
    }
}

// ---------------------------------------------------------------------------
// Rescore: exact fp32 s = x.e - cbn/2 for candidates within margin; pick best
// (first-index tie-break), write x_q, per-token loss partial. 1 warp/token.
// ---------------------------------------------------------------------------
__global__ __launch_bounds__(256)
void k_rescore(const float* __restrict__ x, const float* __restrict__ cb,
               float* __restrict__ xq) {
    const int t = blockIdx.x * 8 + (threadIdx.x >> 5);
    const int lane = threadIdx.x & 31;
    float4 x4 = reinterpret_cast<const float4*>(x)[(size_t)t * 32 + lane];

    float v = __int_as_float(0xff800000);
    uint32_t ci = 0;
    if (lane < 24) {
        uint2 cd = g_cand[(size_t)t * 24 + lane];
        v = __uint_as_float(cd.x); ci = cd.y;
    }
    float vmax = v;
#pragma unroll
    for (int o = 16; o; o >>= 1) vmax = fmaxf(vmax, __shfl_xor_sync(0xffffffffu, vmax, o));
    const float thr = vmax - 0.4f;

    float bs = __int_as_float(0xff800000);
    int bi = 0x7fffffff;
    float4 be = x4;
#pragma unroll
    for (int j = 0; j < 24; j++) {
        float vj = __shfl_sync(0xffffffffu, v, j);
        if (vj < thr) continue;
        int ij = (int)__shfl_sync(0xffffffffu, ci, j);
        float4 e4 = reinterpret_cast<const float4*>(cb)[(size_t)ij * 32 + lane];
        float p = x4.x * e4.x + x4.y * e4.y + x4.z * e4.z + x4.w * e4.w;
#pragma unroll
        for (int o = 16; o; o >>= 1) p += __shfl_xor_sync(0xffffffffu, p, o);
        float s = p - 0.5f * g_cbnorm[ij];
        if (s > bs || (s == bs && ij < bi)) { bs = s; bi = ij; be = e4; }
    }

    float4 q4;
    q4.x = x4.x + (be.x - x4.x);
    q4.y = x4.y + (be.y - x4.y);
    q4.z = x4.z + (be.z - x4.z);
    q4.w = x4.w + (be.w - x4.w);
    reinterpret_cast<float4*>(xq)[(size_t)t * 32 + lane] = q4;
    float d0 = q4.x - x4.x, d1 = q4.y - x4.y, d2 = q4.z - x4.z, d3 = q4.w - x4.w;
    float tl = d0 * d0 + d1 * d1 + d2 * d2 + d3 * d3;
#pragma unroll
    for (int o = 16; o; o >>= 1) tl += __shfl_xor_sync(0xffffffffu, tl, o);
    if (lane == 0) g_tokloss[t] = tl;
}

// ---------------------------------------------------------------------------
__global__ __launch_bounds__(128)
void k_loss(float* __restrict__ loss) {
    int g = blockIdx.x;
    int lane = threadIdx.x & 31, warp = threadIdx.x >> 5;
    float v = g_tokloss[g * 128 + threadIdx.x];
#pragma unroll
    for (int o = 16; o; o >>= 1) v += __shfl_xor_sync(0xffffffffu, v, o);
    __shared__ float ws[4];
    if (lane == 0) ws[warp] = v;
    __syncthreads();
    if (threadIdx.x == 0)
        loss[g] = (ws[0] + ws[1] + ws[2] + ws[3]) * (1.25f / 16384.0f);
}

// ---------------------------------------------------------------------------
extern "C" void kernel_launch(void* const* d_in, const int* in_sizes, int n_in,
                              void* d_out, int out_size) {
    const float* x  = (const float*)d_in[0];
    const float* cb = (const float*)d_in[1];
    float* xq = (float*)d_out;
    float* loss;
    if (out_size >= TT * DD + GROUPS) {
        loss = xq + (size_t)TT * DD;
    } else {
        void* p = nullptr;
        cudaGetSymbolAddress(&p, g_loss_dummy);
        loss = (float*)p;
    }
    cudaFuncSetAttribute(k_gemm, cudaFuncAttributeMaxDynamicSharedMemorySize, SMEM_SZ);
    k_prep<<<KK / 8, 256>>>(cb);
    k_gemm<<<TT / 128, 256, SMEM_SZ>>>(x);
    k_rescore<<<TT / 8, 256>>>(x, cb, xq);
    k_loss<<<GROUPS, 128>>>(loss);
}

// round 7
// speedup vs baseline: 3.1946x; 1.0965x over previous
#include <cuda_runtime.h>
#include <cuda_fp16.h>
#include <stdint.h>

#define TT 65536
#define DD 128
#define KK 1024
#define GROUPS 512

// baked codebook: 1024 rows x 128 f16 = 256 B per row
__device__ uint4  Eb[KK * 16];
__device__ float  g_cbnorm[KK];
__device__ uint2  g_cand[TT * 24];      // per token: 8 subsets x top-3 (v_bits, idx)
__device__ float  g_tokloss[TT];
__device__ float  g_loss_dummy[GROUPS];

__device__ __forceinline__ uint32_t smem_u32(const void* p) {
    uint32_t a;
    asm("{ .reg .u64 t; cvta.to.shared.u64 t, %1; cvt.u32.u64 %0, t; }" : "=r"(a) : "l"(p));
    return a;
}
__device__ __forceinline__ uint32_t h2u(float a, float b) {
    __half2 t = __floats2half2_rn(a, b);
    return *reinterpret_cast<uint32_t*>(&t);
}
#define CP_ASYNC16(s, g) asm volatile("cp.async.cg.shared.global [%0], [%1], 16;" :: "r"(s), "l"(g) : "memory")
#define CP_COMMIT()      asm volatile("cp.async.commit_group;" ::: "memory")
#define CP_WAIT(n)       asm volatile("cp.async.wait_group %0;" :: "n"(n) : "memory")

#define LDSM4(r0, r1, r2, r3, a) \
    asm volatile("ldmatrix.sync.aligned.m8n8.x4.shared.b16 {%0,%1,%2,%3}, [%4];" \
        : "=r"(r0), "=r"(r1), "=r"(r2), "=r"(r3) : "r"(a))

// f16 accumulate: D,C are 2x f16x2 regs -> 2x rate vs f32 acc on legacy pipe
#define MMA16816H(d, a, b) \
    asm volatile("mma.sync.aligned.m16n8k16.row.col.f16.f16.f16.f16 " \
        "{%0,%1}, {%2,%3,%4,%5}, {%6,%7}, {%0,%1};" \
        : "+r"((d)[0]), "+r"((d)[1]) \
        : "r"((a)[0]), "r"((a)[1]), "r"((a)[2]), "r"((a)[3]), "r"((b)[0]), "r"((b)[1]))

// SMEM: A 128x272B | B0 128x272B | B1 128x272B | cbn/2 1024 f32
#define TILE_B    34816
#define CBN_OFF   (3 * TILE_B)
#define SMEM_SZ   (3 * TILE_B + 4096)

// ---------------------------------------------------------------------------
// Prep: codebook -> f16 rows + norms. One warp per code.
// ---------------------------------------------------------------------------
__global__ void k_prep(const float* __restrict__ cb) {
    int warp = threadIdx.x >> 5, lane = threadIdx.x & 31;
    int k = (blockIdx.x << 3) + warp;
    float4 v = reinterpret_cast<const float4*>(cb)[k * 32 + lane];
    float n = v.x * v.x + v.y * v.y + v.z * v.z + v.w * v.w;
#pragma unroll
    for (int o = 16; o; o >>= 1) n += __shfl_xor_sync(0xffffffffu, n, o);
    uint2* row = reinterpret_cast<uint2*>(Eb) + (size_t)k * 32;
    uint2 w;
    w.x = h2u(v.x, v.y); w.y = h2u(v.z, v.w);
    row[lane] = w;
    if (lane == 0) g_cbnorm[k] = n;
}

// ---------------------------------------------------------------------------
// GEMM: s[t][k] = x_t . e_k (f16 acc) - ||e_k||^2/2 (f32 epilogue),
// per-subset top-3. CTA: 128 tokens x 1024 codes (8 chunks of 128).
// 8 warps = 4(m) x 2(n).
// ---------------------------------------------------------------------------
__global__ __launch_bounds__(256, 1)
void k_gemm(const float* __restrict__ x) {
    extern __shared__ char smc[];
    const uint32_t sb = smem_u32(smc);
    float* csm = reinterpret_cast<float*>(smc + CBN_OFF);
    const int tid = threadIdx.x, warp = tid >> 5, lane = tid & 31;
    const int warp_m = warp >> 1, warp_n = warp & 1;
    const int tok0 = blockIdx.x << 7;

    // cbn/2 table
#pragma unroll
    for (int i = 0; i < 4; i++) csm[tid + i * 256] = 0.5f * g_cbnorm[tid + i * 256];

    // Build A: 128 rows x 128 f16 (272B stride). Thread: row tid/2, half tid&1.
    {
        int r = tid >> 1, h = tid & 1;
        const float4* xr = reinterpret_cast<const float4*>(x + (size_t)(tok0 + r) * 128 + h * 64);
        char* dst = smc + r * 272 + h * 128;
#pragma unroll
        for (int i = 0; i < 8; i++) {
            float4 a = xr[i * 2], b = xr[i * 2 + 1];
            uint4 u;
            u.x = h2u(a.x, a.y); u.y = h2u(a.z, a.w);
            u.z = h2u(b.x, b.y); u.w = h2u(b.z, b.w);
            *reinterpret_cast<uint4*>(dst + i * 16) = u;
        }
    }

    // prefetch B chunk 0 (128 rows x 256B = 2048 x 16B)
    {
        const char* src = reinterpret_cast<const char*>(Eb);
        uint32_t bs = sb + TILE_B;
#pragma unroll
        for (int j = 0; j < 8; j++) {
            int e = tid + j * 256;
            int row = e >> 4, c = e & 15;
            CP_ASYNC16(bs + row * 272 + c * 16, src + row * 256 + c * 16);
        }
        CP_COMMIT();
    }

    float v0[4], v1[4], v2[4];
    int   i0[4], i1[4], i2[4];
#pragma unroll
    for (int s = 0; s < 4; s++) {
        v0[s] = v1[s] = v2[s] = __int_as_float(0xff800000);
        i0[s] = i1[s] = i2[s] = 0x7fffffff;
    }

    __syncthreads();

    for (int c = 0; c < 8; c++) {
        if (c + 1 < 8) {
            const char* src = reinterpret_cast<const char*>(Eb) + (size_t)(c + 1) * 32768;
            uint32_t bs = sb + TILE_B + ((c + 1) & 1) * TILE_B;
#pragma unroll
            for (int j = 0; j < 8; j++) {
                int e = tid + j * 256;
                int row = e >> 4, cc = e & 15;
                CP_ASYNC16(bs + row * 272 + cc * 16, src + row * 256 + cc * 16);
            }
            CP_COMMIT();
            CP_WAIT(1);
        } else {
            CP_WAIT(0);
        }
        __syncthreads();   // chunk c resident in buffer c&1

        const uint32_t Bb = sb + TILE_B + (c & 1) * TILE_B;
        uint32_t acc[2][8][2];
#pragma unroll
        for (int mb = 0; mb < 2; mb++)
#pragma unroll
            for (int nb = 0; nb < 8; nb++) { acc[mb][nb][0] = 0u; acc[mb][nb][1] = 0u; }

        const uint32_t aAddr0 = sb + (warp_m * 32 + (lane & 15)) * 272 + (lane >> 4) * 16;
        const uint32_t bAddr0 = Bb + (warp_n * 64 + ((lane >> 4) << 3) + (lane & 7)) * 272;
        const uint32_t bHalf = ((lane >> 3) & 1) * 16;

#pragma unroll
        for (int k = 0; k < 8; k++) {
            uint32_t a[2][4];
#pragma unroll
            for (int mb = 0; mb < 2; mb++)
                LDSM4(a[mb][0], a[mb][1], a[mb][2], a[mb][3],
                      aAddr0 + mb * 16 * 272 + k * 32);
            uint32_t b[4][4];
#pragma unroll
            for (int np = 0; np < 4; np++)
                LDSM4(b[np][0], b[np][1], b[np][2], b[np][3],
                      bAddr0 + np * 16 * 272 + bHalf + k * 32);
#pragma unroll
            for (int mb = 0; mb < 2; mb++)
#pragma unroll
                for (int np = 0; np < 4; np++) {
                    MMA16816H(acc[mb][np * 2],     a[mb], (&b[np][0]));
                    MMA16816H(acc[mb][np * 2 + 1], a[mb], (&b[np][2]));
                }
        }

        // epilogue: unpack f16x2, apply -||e||^2/2, top-3 insertion
        const int base = c * 128 + warp_n * 64 + ((lane & 3) << 1);
#pragma unroll
        for (int mb = 0; mb < 2; mb++)
#pragma unroll
            for (int dd = 0; dd < 2; dd++) {
                const int s = mb * 2 + dd;
#pragma unroll
                for (int nb = 0; nb < 8; nb++) {
                    float2 pv = __half22float2(
                        *reinterpret_cast<__half2*>(&acc[mb][nb][dd]));
#pragma unroll
                    for (int e = 0; e < 2; e++) {
                        int idx = base + nb * 8 + e;
                        float vv = (e ? pv.y : pv.x) - csm[idx];
                        if (vv > v2[s]) {
                            if (vv > v0[s]) {
                                v2[s] = v1[s]; i2[s] = i1[s];
                                v1[s] = v0[s]; i1[s] = i0[s];
                                v0[s] = vv;    i0[s] = idx;
                            } else if (vv > v1[s]) {
                                v2[s] = v1[s]; i2[s] = i1[s];
                                v1[s] = vv;    i1[s] = idx;
                            } else {
                                v2[s] = vv;    i2[s] = idx;
                            }
                        }
                    }
                }
            }
        __syncthreads();   // done reading buffer c&1
    }

    // 8 disjoint subsets per token: (warp_n, lane&3). No collisions.
    const int sub = warp_n * 4 + (lane & 3);
#pragma unroll
    for (int s = 0; s < 4; s++) {
        int token = tok0 + warp_m * 32 + (s >> 1) * 16 + (lane >> 2) + (s & 1) * 8;
        uint2* dst = g_cand + (size_t)token * 24 + sub * 3;
        dst[0] = make_uint2(__float_as_uint(v0[s]), (uint32_t)i0[s]);
        dst[1] = make_uint2(__float_as_uint(v1[s]), (uint32_t)i1[s]);
        dst[2] = make_uint2(__float_as_uint(v2[s]), (uint32_t)i2[s]);
    }
}

// ---------------------------------------------------------------------------
// Rescore: exact fp32 s = x.e - cbn/2 for candidates within margin (ballot-
// pruned); pick best (first-index tie-break), write x_q, token loss partial.
// ---------------------------------------------------------------------------
__global__ __launch_bounds__(256)
void k_rescore(const float* __restrict__ x, const float* __restrict__ cb,
               float* __restrict__ xq) {
    const int t = blockIdx.x * 8 + (threadIdx.x >> 5);
    const int lane = threadIdx.x & 31;
    float4 x4 = reinterpret_cast<const float4*>(x)[(size_t)t * 32 + lane];

    float v = __int_as_float(0xff800000);
    uint32_t ci = 0;
    if (lane < 24) {
        uint2 cd = g_cand[(size_t)t * 24 + lane];
        v = __uint_as_float(cd.x); ci = cd.y;
    }
    float vmax = v;
#pragma unroll
    for (int o = 16; o; o >>= 1) vmax = fmaxf(vmax, __shfl_xor_sync(0xffffffffu, vmax, o));
    const float thr = vmax - 0.5f;

    uint32_t m = __ballot_sync(0xffffffffu, v >= thr);
    float bs = __int_as_float(0xff800000);
    int bi = 0x7fffffff;
    float4 be = x4;
    while (m) {
        int j = __ffs(m) - 1;
        m &= m - 1;
        int ij = (int)__shfl_sync(0xffffffffu, ci, j);
        float4 e4 = reinterpret_cast<const float4*>(cb)[(size_t)ij * 32 + lane];
        float p = x4.x * e4.x + x4.y * e4.y + x4.z * e4.z + x4.w * e4.w;
#pragma unroll
        for (int o = 16; o; o >>= 1) p += __shfl_xor_sync(0xffffffffu, p, o);
        float s = p - 0.5f * g_cbnorm[ij];
        if (s > bs || (s == bs && ij < bi)) { bs = s; bi = ij; be = e4; }
    }

    float4 q4;
    q4.x = x4.x + (be.x - x4.x);
    q4.y = x4.y + (be.y - x4.y);
    q4.z = x4.z + (be.z - x4.z);
    q4.w = x4.w + (be.w - x4.w);
    reinterpret_cast<float4*>(xq)[(size_t)t * 32 + lane] = q4;
    float d0 = q4.x - x4.x, d1 = q4.y - x4.y, d2 = q4.z - x4.z, d3 = q4.w - x4.w;
    float tl = d0 * d0 + d1 * d1 + d2 * d2 + d3 * d3;
#pragma unroll
    for (int o = 16; o; o >>= 1) tl += __shfl_xor_sync(0xffffffffu, tl, o);
    if (lane == 0) g_tokloss[t] = tl;
}

// ---------------------------------------------------------------------------
__global__ __launch_bounds__(128)
void k_loss(float* __restrict__ loss) {
    int g = blockIdx.x;
    int lane = threadIdx.x & 31, warp = threadIdx.x >> 5;
    float v = g_tokloss[g * 128 + threadIdx.x];
#pragma unroll
    for (int o = 16; o; o >>= 1) v += __shfl_xor_sync(0xffffffffu, v, o);
    __shared__ float ws[4];
    if (lane == 0) ws[warp] = v;
    __syncthreads();
    if (threadIdx.x == 0)
        loss[g] = (ws[0] + ws[1] + ws[2] + ws[3]) * (1.25f / 16384.0f);
}

// ---------------------------------------------------------------------------
extern "C" void kernel_launch(void* const* d_in, const int* in_sizes, int n_in,
                              void* d_out, int out_size) {
    const float* x  = (const float*)d_in[0];
    const float* cb = (const float*)d_in[1];
    float* xq = (float*)d_out;
    float* loss;
    if (out_size >= TT * DD + GROUPS) {
        loss = xq + (size_t)TT * DD;
    } else {
        void* p = nullptr;
        cudaGetSymbolAddress(&p, g_loss_dummy);
        loss = (float*)p;
    }
    cudaFuncSetAttribute(k_gemm, cudaFuncAttributeMaxDynamicSharedMemorySize, SMEM_SZ);
    k_prep<<<KK / 8, 256>>>(cb);
    k_gemm<<<TT / 128, 256, SMEM_SZ>>>(x);
    k_rescore<<<TT / 8, 256>>>(x, cb, xq);
    k_loss<<<GROUPS, 128>>>(loss);
}

// round 10
// speedup vs baseline: 3.7683x; 1.1796x over previous
#include <cuda_runtime.h>
#include <cuda_fp16.h>
#include <stdint.h>

#define TT 65536
#define DD 128
#define KK 1024
#define GROUPS 512
#define NCH 16            // chunks of 64 codes
#define CAP 64            // candidate list capacity per token
#define MARGIN 1.0f

// baked codebook: 1024 rows x 288B (144 f16: e[128], -cbn/2 hi, lo, zeros)
__device__ uint4    Eb[KK * 18];
__device__ float    g_cbnorm[KK];
__device__ uint32_t g_cnt[TT];
__device__ uint16_t g_list[TT * CAP];
__device__ float    g_loss_dummy[GROUPS];

__device__ __forceinline__ uint32_t smem_u32(const void* p) {
    uint32_t a;
    asm("{ .reg .u64 t; cvta.to.shared.u64 t, %1; cvt.u32.u64 %0, t; }" : "=r"(a) : "l"(p));
    return a;
}
__device__ __forceinline__ uint32_t h2u(float a, float b) {
    __half2 t = __floats2half2_rn(a, b);
    return *reinterpret_cast<uint32_t*>(&t);
}
// order-preserving f32 <-> u32 (for atomicMax over signed floats)
__device__ __forceinline__ uint32_t encf(float v) {
    uint32_t u = __float_as_uint(v);
    return ((int)u < 0) ? ~u : (u | 0x80000000u);
}
// FIXED: high bit set => encoded positive (undo the OR); clear => encoded negative (~u)
__device__ __forceinline__ float decf(uint32_t u) {
    return __uint_as_float(((int)u < 0) ? (u & 0x7fffffffu) : ~u);
}
#define CP_ASYNC16(s, g) asm volatile("cp.async.cg.shared.global [%0], [%1], 16;" :: "r"(s), "l"(g) : "memory")
#define CP_COMMIT()      asm volatile("cp.async.commit_group;" ::: "memory")
#define CP_WAIT(n)       asm volatile("cp.async.wait_group %0;" :: "n"(n) : "memory")

#define LDSM4(r0, r1, r2, r3, a) \
    asm volatile("ldmatrix.sync.aligned.m8n8.x4.shared.b16 {%0,%1,%2,%3}, [%4];" \
        : "=r"(r0), "=r"(r1), "=r"(r2), "=r"(r3) : "r"(a))

#define MMA16816H(d, a, b) \
    asm volatile("mma.sync.aligned.m16n8k16.row.col.f16.f16.f16.f16 " \
        "{%0,%1}, {%2,%3,%4,%5}, {%6,%7}, {%0,%1};" \
        : "+r"((d)[0]), "+r"((d)[1]) \
        : "r"((a)[0]), "r"((a)[1]), "r"((a)[2]), "r"((a)[3]), "r"((b)[0]), "r"((b)[1]))

// SMEM layout (bytes): A 128x304 | B0 64x304 | B1 64x304 | vmax 512 | cnt 512 | lists 16384
#define A_OFF    0
#define B_OFF    38912
#define B_STRIDE 19456
#define VM_OFF   77824
#define CN_OFF   78336
#define LS_OFF   78848
#define SMEM_SZ  95232

// ---------------------------------------------------------------------------
// Prep: codebook -> f16 rows [e | -cbn/2 hi,lo | 0...] + norms. 1 warp/code.
// ---------------------------------------------------------------------------
__global__ void k_prep(const float* __restrict__ cb) {
    int warp = threadIdx.x >> 5, lane = threadIdx.x & 31;
    int k = (blockIdx.x << 3) + warp;
    float4 v = reinterpret_cast<const float4*>(cb)[k * 32 + lane];
    float n = v.x * v.x + v.y * v.y + v.z * v.z + v.w * v.w;
#pragma unroll
    for (int o = 16; o; o >>= 1) n += __shfl_xor_sync(0xffffffffu, n, o);
    uint2* row = reinterpret_cast<uint2*>(Eb) + (size_t)k * 36;
    uint2 w; w.x = h2u(v.x, v.y); w.y = h2u(v.z, v.w);
    row[lane] = w;
    if (lane == 0) {
        g_cbnorm[k] = n;
        float m = -0.5f * n;
        float hi = __half2float(__float2half_rn(m));
        float lo = m - hi;
        uint2 z; z.x = h2u(m, lo); z.y = 0u;
        row[32] = z;
        uint2 zz; zz.x = 0u; zz.y = 0u;
        row[33] = zz;
    }
    if (lane == 1) {
        uint2 zz; zz.x = 0u; zz.y = 0u;
        row[34] = zz; row[35] = zz;
    }
}

// ---------------------------------------------------------------------------
// GEMM + threshold emission.
// CTA = 128 tokens x 1024 codes in 16 chunks of 64. 8 warps = 4(m) x 2(n).
// s[t][k] = x.e - ||e||^2/2 computed fully inside f16 mma (norm K-columns).
// ---------------------------------------------------------------------------
__global__ __launch_bounds__(256, 2)
void k_gemm(const float* __restrict__ x) {
    extern __shared__ char smc[];
    const uint32_t sb = smem_u32(smc);
    uint32_t* vmax = reinterpret_cast<uint32_t*>(smc + VM_OFF);
    uint32_t* cnt  = reinterpret_cast<uint32_t*>(smc + CN_OFF);
    uint16_t* list = reinterpret_cast<uint16_t*>(smc + LS_OFF);
    const int tid = threadIdx.x, warp = tid >> 5, lane = tid & 31;
    const int warp_m = warp >> 1, warp_n = warp & 1;
    const int lg = lane >> 2;
    const int tok0 = blockIdx.x << 7;

    if (tid < 128) { vmax[tid] = 0u; cnt[tid] = 0u; }

    // Build A: 128 rows x 144 f16 (304B stride). Thread: row tid/2, half tid&1.
    {
        int r = tid >> 1, h = tid & 1;
        const float4* xr = reinterpret_cast<const float4*>(x + (size_t)(tok0 + r) * 128 + h * 64);
        char* dst = smc + r * 304 + h * 128;
#pragma unroll
        for (int i = 0; i < 8; i++) {
            float4 a = xr[i * 2], b = xr[i * 2 + 1];
            uint4 u;
            u.x = h2u(a.x, a.y); u.y = h2u(a.z, a.w);
            u.z = h2u(b.x, b.y); u.w = h2u(b.z, b.w);
            *reinterpret_cast<uint4*>(dst + i * 16) = u;
        }
        if (h == 1) {   // cols 128..143 = {1,1,0,...,0}
            uint4 u1; u1.x = h2u(1.0f, 1.0f); u1.y = 0u; u1.z = 0u; u1.w = 0u;
            *reinterpret_cast<uint4*>(smc + r * 304 + 256) = u1;
            uint4 u0; u0.x = 0u; u0.y = 0u; u0.z = 0u; u0.w = 0u;
            *reinterpret_cast<uint4*>(smc + r * 304 + 272) = u0;
        }
    }

    // prefetch chunk 0 (64 rows x 288B = 1152 x 16B)
    {
        const char* src = reinterpret_cast<const char*>(Eb);
        uint32_t bs = sb + B_OFF;
#pragma unroll
        for (int j = 0; j < 5; j++) {
            int e = tid + j * 256;
            if (e < 1152) CP_ASYNC16(bs + (e / 18) * 304 + (e % 18) * 16, src + (e / 18) * 288 + (e % 18) * 16);
        }
        CP_COMMIT();
    }

    const uint32_t aAddr0 = sb + (warp_m * 32 + (lane & 15)) * 304 + (lane >> 4) * 16;
    const uint32_t cellBase = ((warp_m * 8 + lg) << 2);

    for (int c = 0; c < NCH; c++) {
        if (c + 1 < NCH) {
            const char* src = reinterpret_cast<const char*>(Eb) + (size_t)(c + 1) * 18432;
            uint32_t bs = sb + B_OFF + ((c + 1) & 1) * B_STRIDE;
#pragma unroll
            for (int j = 0; j < 5; j++) {
                int e = tid + j * 256;
                if (e < 1152) CP_ASYNC16(bs + (e / 18) * 304 + (e % 18) * 16, src + (e / 18) * 288 + (e % 18) * 16);
            }
            CP_COMMIT();
            CP_WAIT(1);
        } else {
            CP_WAIT(0);
        }
        __syncthreads();   // chunk c resident; prior-chunk vmax updates visible

        const uint32_t Bb = sb + B_OFF + (c & 1) * B_STRIDE;
        uint32_t acc[2][4][2];
#pragma unroll
        for (int mb = 0; mb < 2; mb++)
#pragma unroll
            for (int nb = 0; nb < 4; nb++) { acc[mb][nb][0] = 0u; acc[mb][nb][1] = 0u; }

        const uint32_t bAddr0 = Bb + (warp_n * 32 + ((lane >> 4) << 3) + (lane & 7)) * 304;
        const uint32_t bHalf = ((lane >> 3) & 1) * 16;

#pragma unroll
        for (int k = 0; k < 9; k++) {
            uint32_t a[2][4];
#pragma unroll
            for (int mb = 0; mb < 2; mb++)
                LDSM4(a[mb][0], a[mb][1], a[mb][2], a[mb][3],
                      aAddr0 + mb * 16 * 304 + k * 32);
            uint32_t b[2][4];
#pragma unroll
            for (int np = 0; np < 2; np++)
                LDSM4(b[np][0], b[np][1], b[np][2], b[np][3],
                      bAddr0 + np * 16 * 304 + bHalf + k * 32);
#pragma unroll
            for (int mb = 0; mb < 2; mb++)
#pragma unroll
                for (int np = 0; np < 2; np++) {
                    MMA16816H(acc[mb][np * 2],     a[mb], (&b[np][0]));
                    MMA16816H(acc[mb][np * 2 + 1], a[mb], (&b[np][2]));
                }
        }

        if (c == 0) {   // seed vmax with chunk-0 per-slot maxima
#pragma unroll
            for (int mb = 0; mb < 2; mb++)
#pragma unroll
                for (int dd = 0; dd < 2; dd++) {
                    __half2 h2 = __hmax2(
                        __hmax2(*reinterpret_cast<__half2*>(&acc[mb][0][dd]),
                                *reinterpret_cast<__half2*>(&acc[mb][1][dd])),
                        __hmax2(*reinterpret_cast<__half2*>(&acc[mb][2][dd]),
                                *reinterpret_cast<__half2*>(&acc[mb][3][dd])));
                    float m = __half2float(__hmax(__low2half(h2), __high2half(h2)));
                    atomicMax(&vmax[cellBase + mb * 2 + dd], encf(m));
                }
            __syncthreads();
        }

        // scan & emit
        uint4 vm4 = *reinterpret_cast<uint4*>(&vmax[cellBase]);
        __half2 thr2[4];
        thr2[0] = __half2half2(__float2half_rd(decf(vm4.x) - MARGIN));
        thr2[1] = __half2half2(__float2half_rd(decf(vm4.y) - MARGIN));
        thr2[2] = __half2half2(__float2half_rd(decf(vm4.z) - MARGIN));
        thr2[3] = __half2half2(__float2half_rd(decf(vm4.w) - MARGIN));
#pragma unroll
        for (int mb = 0; mb < 2; mb++)
#pragma unroll
            for (int dd = 0; dd < 2; dd++) {
                const int s = mb * 2 + dd;
#pragma unroll
                for (int nb = 0; nb < 4; nb++) {
                    uint32_t mask = __hgt2_mask(
                        *reinterpret_cast<__half2*>(&acc[mb][nb][dd]), thr2[s]);
                    if (mask) {
                        float2 pv = __half22float2(*reinterpret_cast<__half2*>(&acc[mb][nb][dd]));
                        int tl = warp_m * 32 + lg + dd * 8 + mb * 16;
                        int code = c * 64 + warp_n * 32 + nb * 8 + ((lane & 3) << 1);
                        if (mask & 0xffffu) {
                            uint32_t p = atomicAdd(&cnt[tl], 1u);
                            if (p < CAP) list[tl * CAP + p] = (uint16_t)code;
                            atomicMax(&vmax[cellBase + s], encf(pv.x));
                        }
                        if (mask >> 16) {
                            uint32_t p = atomicAdd(&cnt[tl], 1u);
                            if (p < CAP) list[tl * CAP + p] = (uint16_t)(code + 1);
                            atomicMax(&vmax[cellBase + s], encf(pv.y));
                        }
                    }
                }
            }
        __syncthreads();   // all reads of buffer c&1 done before it is re-filled
    }

    if (tid < 128) {
        uint32_t n = cnt[tid];
        if (n > CAP) n = CAP;
        g_cnt[tok0 + tid] = n;
        const uint4* s4 = reinterpret_cast<const uint4*>(list + tid * CAP);
        uint4* d4 = reinterpret_cast<uint4*>(g_list + (size_t)(tok0 + tid) * CAP);
#pragma unroll
        for (int i = 0; i < 8; i++) d4[i] = s4[i];
    }
}

// ---------------------------------------------------------------------------
// Rescore (exact fp32) + gather + fused group loss. Block = 1 group (128
// tokens): 1024 threads = 32 warps x 4 tokens. Deterministic reduction.
// ---------------------------------------------------------------------------
__global__ __launch_bounds__(1024)
void k_rescore(const float* __restrict__ x, const float* __restrict__ cb,
               float* __restrict__ xq, float* __restrict__ loss) {
    const int g = blockIdx.x;
    const int warp = threadIdx.x >> 5, lane = threadIdx.x & 31;
    __shared__ float ws[32];
    float wacc = 0.0f;

    for (int i = 0; i < 4; i++) {
        int t = g * 128 + warp * 4 + i;
        int n = (int)g_cnt[t];
        float4 x4 = reinterpret_cast<const float4*>(x)[(size_t)t * 32 + lane];
        float bs = __int_as_float(0xff800000);
        int bi = 0x7fffffff;
        float4 be = x4;
        for (int j = 0; j < n; j++) {
            int ij = (int)g_list[(size_t)t * CAP + j];
            float4 e4 = reinterpret_cast<const float4*>(cb)[(size_t)ij * 32 + lane];
            float p = x4.x * e4.x + x4.y * e4.y + x4.z * e4.z + x4.w * e4.w;
#pragma unroll
            for (int o = 16; o; o >>= 1) p += __shfl_xor_sync(0xffffffffu, p, o);
            float s = p - 0.5f * g_cbnorm[ij];
            if (s > bs || (s == bs && ij < bi)) { bs = s; bi = ij; be = e4; }
        }
        float4 q4;
        q4.x = x4.x + (be.x - x4.x);
        q4.y = x4.y + (be.y - x4.y);
        q4.z = x4.z + (be.z - x4.z);
        q4.w = x4.w + (be.w - x4.w);
        reinterpret_cast<float4*>(xq)[(size_t)t * 32 + lane] = q4;
        float d0 = q4.x - x4.x, d1 = q4.y - x4.y, d2 = q4.z - x4.z, d3 = q4.w - x4.w;
        float tl = d0 * d0 + d1 * d1 + d2 * d2 + d3 * d3;
#pragma unroll
        for (int o = 16; o; o >>= 1) tl += __shfl_xor_sync(0xffffffffu, tl, o);
        if (lane == 0) wacc += tl;
    }
    if (lane == 0) ws[warp] = wacc;
    __syncthreads();
    if (threadIdx.x == 0) {
        float s = 0.0f;
#pragma unroll
        for (int w = 0; w < 32; w++) s += ws[w];
        loss[g] = s * (1.25f / 16384.0f);
    }
}

// ---------------------------------------------------------------------------
extern "C" void kernel_launch(void* const* d_in, const int* in_sizes, int n_in,
                              void* d_out, int out_size) {
    const float* x  = (const float*)d_in[0];
    const float* cb = (const float*)d_in[1];
    float* xq = (float*)d_out;
    float* loss;
    if (out_size >= TT * DD + GROUPS) {
        loss = xq + (size_t)TT * DD;
    } else {
        void* p = nullptr;
        cudaGetSymbolAddress(&p, g_loss_dummy);
        loss = (float*)p;
    }
    cudaFuncSetAttribute(k_gemm, cudaFuncAttributeMaxDynamicSharedMemorySize, SMEM_SZ);
    k_prep<<<KK / 8, 256>>>(cb);
    k_gemm<<<TT / 128, 256, SMEM_SZ>>>(x);
    k_rescore<<<GROUPS, 1024>>>(x, cb, xq, loss);
}